// round 3
// baseline (speedup 1.0000x reference)
#include <cuda_runtime.h>
#include <cstdint>

#define DIM   64
#define ODIM  16
#define NMAX  100000
#define GMAX  512

// ---- scratch (no allocations allowed; __device__ globals per rules) ----
// 16B alignment is REQUIRED: red.global.add.v4.f32 traps on misaligned targets.
__device__ __align__(16) float d_agg[(size_t)NMAX * DIM];
__device__ __align__(16) float d_h1 [(size_t)NMAX * DIM];
__device__ float d_cnt[NMAX];
__device__ __align__(16) float d_pool[(size_t)GMAX * DIM];
__device__ float d_gcnt[GMAX];

// ---- helpers ----
__device__ __forceinline__ void red_add_v4(float* p, float4 v) {
    asm volatile("red.global.add.v4.f32 [%0], {%1,%2,%3,%4};"
                 :: "l"(p), "f"(v.x), "f"(v.y), "f"(v.z), "f"(v.w) : "memory");
}

__device__ __forceinline__ unsigned long long pack2(float v) {
    unsigned long long r;
    asm("mov.b64 %0, {%1,%1};" : "=l"(r) : "r"(__float_as_uint(v)));
    return r;
}
__device__ __forceinline__ void unpack2(unsigned long long v, float& lo, float& hi) {
    unsigned int a, b;
    asm("mov.b64 {%0,%1}, %2;" : "=r"(a), "=r"(b) : "l"(v));
    lo = __uint_as_float(a); hi = __uint_as_float(b);
}
#define FMA2(acc, a, b) \
    asm("fma.rn.f32x2 %0, %1, %2, %0;" : "+l"(acc) : "l"(a), "l"(b))

// ---- zero scratch ----
__global__ void zero_k(float* __restrict__ p, int n) {
    int i = blockIdx.x * blockDim.x + threadIdx.x;
    int st = gridDim.x * blockDim.x;
    for (; i < n; i += st) p[i] = 0.f;
}

// ---- per-group node counts ----
__global__ void gcnt_k(const int* __restrict__ batch, int n) {
    int i = blockIdx.x * blockDim.x + threadIdx.x;
    if (i < n) atomicAdd(&d_gcnt[batch[i]], 1.0f);
}

// ---- edge scatter: agg[dst] += feat[src]; optionally cnt[dst] += 1 ----
__global__ void scatter_k(const float* __restrict__ feat,
                          const int* __restrict__ ei, int E,
                          float* __restrict__ agg, int docnt) {
    int e = blockIdx.x * blockDim.x + threadIdx.x;
    if (e >= E) return;
    int s = ei[e];
    int d = ei[E + e];
    const float4* xr = (const float4*)(feat + (size_t)s * DIM);
    float* ar = agg + (size_t)d * DIM;
#pragma unroll
    for (int i = 0; i < 16; i++) {
        float4 v = __ldg(xr + i);
        red_add_v4(ar + i * 4, v);
    }
    if (docnt) atomicAdd(&d_cnt[d], 1.0f);
}

// ---- fused SAGE node update: out = relu((agg/cnt) @ Wl^T + b + x @ Wr^T)
//      if batch != nullptr: red-scatter result into d_pool[batch[node]] instead of storing
#define WPAD 68   // padded transposed-weight row stride (floats); 68*4=272 B, 16B-aligned
__global__ __launch_bounds__(256)
void node_k(const float* __restrict__ xin, const float* __restrict__ agg,
            const float* __restrict__ Wl, const float* __restrict__ bl,
            const float* __restrict__ Wr, float* __restrict__ hout,
            const int* __restrict__ batch, int n_nodes) {
    __shared__ __align__(16) float wlT[DIM * WPAD];
    __shared__ __align__(16) float wrT[DIM * WPAD];
    __shared__ float bsh[DIM];
    __shared__ __align__(16) float ash[16 * DIM];
    __shared__ __align__(16) float xsh[16 * DIM];
    __shared__ float invsh[16];

    int tid = threadIdx.x;
    // load weights transposed: wT[k*WPAD + o] = W[o*64 + k]
    for (int i = tid; i < DIM * DIM; i += 256) {
        int o = i >> 6, k = i & 63;
        wlT[k * WPAD + o] = Wl[i];
        wrT[k * WPAD + o] = Wr[i];
    }
    if (tid < DIM) bsh[tid] = bl[tid];

    int base = blockIdx.x * 128;
    int q = tid & 15;       // output quad: outputs [4q, 4q+3]
    int n = tid >> 4;       // node slot within a 16-node round

    for (int r = 0; r < 8; r++) {
        int nb = base + r * 16;
        __syncthreads();   // protects smem reuse (and weight load on r==0)
        {   // stage 16 consecutive node rows (contiguous 4KB) as float4
            long long gi = (long long)nb * DIM + tid * 4;
            float4 va = make_float4(0.f, 0.f, 0.f, 0.f), vx = va;
            if (gi + 3 < (long long)n_nodes * DIM) {
                va = *(const float4*)(agg + gi);
                vx = *(const float4*)(xin + gi);
            }
            *(float4*)&ash[tid * 4] = va;
            *(float4*)&xsh[tid * 4] = vx;
            if (tid < 16) {
                int nd = nb + tid;
                float c = (nd < n_nodes) ? d_cnt[nd] : 1.f;
                invsh[tid] = 1.f / fmaxf(c, 1.f);
            }
        }
        __syncthreads();

        int node = nb + n;
        if (node < n_nodes) {
            const float* ap = &ash[n * DIM];
            const float* xp = &xsh[n * DIM];
            unsigned long long al0 = 0, al1 = 0, ar0 = 0, ar1 = 0;
#pragma unroll
            for (int k = 0; k < DIM; k++) {
                unsigned long long av2 = pack2(ap[k]);
                unsigned long long xv2 = pack2(xp[k]);
                double2 wl = *(const double2*)&wlT[k * WPAD + 4 * q];
                double2 wr = *(const double2*)&wrT[k * WPAD + 4 * q];
                FMA2(al0, av2, __double_as_longlong(wl.x));
                FMA2(al1, av2, __double_as_longlong(wl.y));
                FMA2(ar0, xv2, __double_as_longlong(wr.x));
                FMA2(ar1, xv2, __double_as_longlong(wr.y));
            }
            float l0, l1, l2, l3, r0, r1, r2, r3;
            unpack2(al0, l0, l1); unpack2(al1, l2, l3);
            unpack2(ar0, r0, r1); unpack2(ar1, r2, r3);
            float inv = invsh[n];
            float4 res;
            res.x = fmaxf(fmaf(l0, inv, r0) + bsh[4 * q + 0], 0.f);
            res.y = fmaxf(fmaf(l1, inv, r1) + bsh[4 * q + 1], 0.f);
            res.z = fmaxf(fmaf(l2, inv, r2) + bsh[4 * q + 2], 0.f);
            res.w = fmaxf(fmaf(l3, inv, r3) + bsh[4 * q + 3], 0.f);
            if (batch) {
                int g = batch[node];
                red_add_v4(&d_pool[(size_t)g * DIM + 4 * q], res);
            } else {
                *(float4*)&hout[(size_t)node * DIM + 4 * q] = res;
            }
        }
    }
}

// ---- pooled mean -> fc -> log_softmax ----
__global__ void final_k(const float* __restrict__ fcW, const float* __restrict__ fcb,
                        float* __restrict__ out, int G) {
    int g = blockIdx.x * blockDim.x + threadIdx.x;
    if (g >= G) return;
    float inv = 1.f / fmaxf(d_gcnt[g], 1.f);
    float p[DIM];
    const float* pr = &d_pool[(size_t)g * DIM];
#pragma unroll
    for (int k = 0; k < DIM; k++) p[k] = pr[k] * inv;
    float lg[ODIM];
#pragma unroll
    for (int o = 0; o < ODIM; o++) {
        float s = fcb[o];
        const float* w = &fcW[o * DIM];
#pragma unroll
        for (int k = 0; k < DIM; k++) s = fmaf(p[k], w[k], s);
        lg[o] = s;
    }
    float m = lg[0];
#pragma unroll
    for (int o = 1; o < ODIM; o++) m = fmaxf(m, lg[o]);
    float se = 0.f;
#pragma unroll
    for (int o = 0; o < ODIM; o++) se += expf(lg[o] - m);
    float lse = m + logf(se);
#pragma unroll
    for (int o = 0; o < ODIM; o++) out[g * ODIM + o] = lg[o] - lse;
}

extern "C" void kernel_launch(void* const* d_in, const int* in_sizes, int n_in,
                              void* d_out, int out_size) {
    const float* x   = (const float*)d_in[0];
    const float* W1l = (const float*)d_in[1];
    const float* b1  = (const float*)d_in[2];
    const float* W1r = (const float*)d_in[3];
    const float* W2l = (const float*)d_in[4];
    const float* b2  = (const float*)d_in[5];
    const float* W2r = (const float*)d_in[6];
    const float* fcW = (const float*)d_in[7];
    const float* fcb = (const float*)d_in[8];
    // JAX without x64 silently emits int32 for "int64" randint -> read as int32.
    const int* ei    = (const int*)d_in[9];
    const int* batch = (const int*)d_in[10];

    int N = in_sizes[10];
    int E = in_sizes[9] / 2;
    int G = out_size / ODIM;

    float *agg, *h1, *cnt, *pool, *gcnt;
    cudaGetSymbolAddress((void**)&agg,  d_agg);
    cudaGetSymbolAddress((void**)&h1,   d_h1);
    cudaGetSymbolAddress((void**)&cnt,  d_cnt);
    cudaGetSymbolAddress((void**)&pool, d_pool);
    cudaGetSymbolAddress((void**)&gcnt, d_gcnt);

    zero_k<<<2048, 256>>>(agg, N * DIM);
    zero_k<<<128, 256>>>(cnt, N);
    zero_k<<<32, 256>>>(pool, G * DIM);
    zero_k<<<1, 256>>>(gcnt, G);

    gcnt_k<<<(N + 255) / 256, 256>>>(batch, N);

    // layer 1
    scatter_k<<<(E + 255) / 256, 256>>>(x, ei, E, agg, 1);
    node_k<<<(N + 127) / 128, 256>>>(x, agg, W1l, b1, W1r, h1, nullptr, N);

    // layer 2
    zero_k<<<2048, 256>>>(agg, N * DIM);
    scatter_k<<<(E + 255) / 256, 256>>>(h1, ei, E, agg, 0);
    node_k<<<(N + 127) / 128, 256>>>(h1, agg, W2l, b2, W2r, nullptr, batch, N);

    // pool -> fc -> log_softmax
    final_k<<<(G + 255) / 256, 256>>>(fcW, fcb, (float*)d_out, G);
}

// round 4
// speedup vs baseline: 1.7916x; 1.7916x over previous
#include <cuda_runtime.h>
#include <cstdint>

#define DIM   64
#define ODIM  16
#define NMAX  100000
#define EMAX  1600000
#define GMAX  512
#define NB_SCAN 512   // max blocks for scan level-1 (N/256 = 391 < 512)

// ---- scratch (no allocations allowed; __device__ globals per rules) ----
__device__ __align__(16) float d_agg[(size_t)NMAX * DIM];
__device__ __align__(16) float d_h1 [(size_t)NMAX * DIM];
__device__ __align__(16) float d_pool[(size_t)GMAX * DIM];
__device__ float d_gcnt[GMAX];
__device__ int d_deg[NMAX];
__device__ int d_off[NMAX + 1];
__device__ int d_cur[NMAX];
__device__ int d_col[EMAX];       // src node per dst-sorted edge slot
__device__ int d_bsum[NB_SCAN];

// ---- helpers ----
__device__ __forceinline__ void red_add_v4(float* p, float4 v) {
    asm volatile("red.global.add.v4.f32 [%0], {%1,%2,%3,%4};"
                 :: "l"(p), "f"(v.x), "f"(v.y), "f"(v.z), "f"(v.w) : "memory");
}
__device__ __forceinline__ unsigned long long pack2(float v) {
    unsigned long long r;
    asm("mov.b64 %0, {%1,%1};" : "=l"(r) : "r"(__float_as_uint(v)));
    return r;
}
__device__ __forceinline__ void unpack2(unsigned long long v, float& lo, float& hi) {
    unsigned int a, b;
    asm("mov.b64 {%0,%1}, %2;" : "=r"(a), "=r"(b) : "l"(v));
    lo = __uint_as_float(a); hi = __uint_as_float(b);
}
#define FMA2(acc, a, b) \
    asm("fma.rn.f32x2 %0, %1, %2, %0;" : "+l"(acc) : "l"(a), "l"(b))

// ---- small utility kernels ----
__global__ void zero_f(float* __restrict__ p, int n) {
    int i = blockIdx.x * blockDim.x + threadIdx.x;
    int st = gridDim.x * blockDim.x;
    for (; i < n; i += st) p[i] = 0.f;
}
__global__ void zero_i(int* __restrict__ p, int n) {
    int i = blockIdx.x * blockDim.x + threadIdx.x;
    int st = gridDim.x * blockDim.x;
    for (; i < n; i += st) p[i] = 0;
}
__global__ void gcnt_k(const int* __restrict__ batch, int n) {
    int i = blockIdx.x * blockDim.x + threadIdx.x;
    if (i < n) atomicAdd(&d_gcnt[batch[i]], 1.0f);
}

// ---- CSR build ----
__global__ void count_k(const int* __restrict__ ei, int E) {
    int e = blockIdx.x * blockDim.x + threadIdx.x;
    if (e < E) atomicAdd(&d_deg[ei[E + e]], 1);
}
// level-1: per-256-block exclusive scan of deg -> off (partial), block totals -> bsum
__global__ void scan1_k(int n) {
    __shared__ int sh[256];
    int tid = threadIdx.x;
    int i = blockIdx.x * 256 + tid;
    int v = (i < n) ? d_deg[i] : 0;
    sh[tid] = v;
    __syncthreads();
#pragma unroll
    for (int o = 1; o < 256; o <<= 1) {
        int t = (tid >= o) ? sh[tid - o] : 0;
        __syncthreads();
        if (tid >= o) sh[tid] += t;
        __syncthreads();
    }
    if (i < n) d_off[i] = sh[tid] - v;      // exclusive within block
    if (tid == 255) d_bsum[blockIdx.x] = sh[255];
}
// level-2: single block scans block totals (exclusive, in place)
__global__ void scan2_k(int nb) {
    __shared__ int sh[NB_SCAN];
    int tid = threadIdx.x;
    int v = (tid < nb) ? d_bsum[tid] : 0;
    sh[tid] = v;
    __syncthreads();
#pragma unroll
    for (int o = 1; o < NB_SCAN; o <<= 1) {
        int t = (tid >= o) ? sh[tid - o] : 0;
        __syncthreads();
        if (tid >= o) sh[tid] += t;
        __syncthreads();
    }
    if (tid < nb) d_bsum[tid] = sh[tid] - v;
}
// level-3: add block offsets; init cursors; set off[n] = E
__global__ void scan3_k(int n, int E) {
    int i = blockIdx.x * 256 + threadIdx.x;
    if (i < n) {
        int o = d_off[i] + d_bsum[blockIdx.x];
        d_off[i] = o;
        d_cur[i] = o;
    }
    if (i == 0) d_off[n] = E;
}
__global__ void fill_k(const int* __restrict__ ei, int E) {
    int e = blockIdx.x * blockDim.x + threadIdx.x;
    if (e >= E) return;
    int s = ei[e];
    int d = ei[E + e];
    int p = atomicAdd(&d_cur[d], 1);
    d_col[p] = s;
}

// ---- gather aggregation: agg[node] = mean_{e in CSR[node]} feat[col[e]] ----
// 16 threads per node, each owns one float4 column. No atomics.
__global__ __launch_bounds__(256)
void gather_k(const float* __restrict__ feat, float* __restrict__ agg, int N) {
    int g = blockIdx.x * blockDim.x + threadIdx.x;
    int node = g >> 4;
    int lane = g & 15;
    if (node >= N) return;
    int beg = d_off[node];
    int end = d_off[node + 1];
    float4 acc = make_float4(0.f, 0.f, 0.f, 0.f);
    int e = beg;
    // 4-deep software pipeline on the index+row loads for MLP
    for (; e + 4 <= end; e += 4) {
        int s0 = d_col[e], s1 = d_col[e + 1], s2 = d_col[e + 2], s3 = d_col[e + 3];
        float4 v0 = __ldg((const float4*)(feat + (size_t)s0 * DIM) + lane);
        float4 v1 = __ldg((const float4*)(feat + (size_t)s1 * DIM) + lane);
        float4 v2 = __ldg((const float4*)(feat + (size_t)s2 * DIM) + lane);
        float4 v3 = __ldg((const float4*)(feat + (size_t)s3 * DIM) + lane);
        acc.x += (v0.x + v1.x) + (v2.x + v3.x);
        acc.y += (v0.y + v1.y) + (v2.y + v3.y);
        acc.z += (v0.z + v1.z) + (v2.z + v3.z);
        acc.w += (v0.w + v1.w) + (v2.w + v3.w);
    }
    for (; e < end; e++) {
        int s = d_col[e];
        float4 v = __ldg((const float4*)(feat + (size_t)s * DIM) + lane);
        acc.x += v.x; acc.y += v.y; acc.z += v.z; acc.w += v.w;
    }
    int deg = end - beg;
    float inv = 1.f / (float)max(deg, 1);
    acc.x *= inv; acc.y *= inv; acc.z *= inv; acc.w *= inv;
    *(float4*)(agg + (size_t)node * DIM + lane * 4) = acc;
}

// ---- fused SAGE node update: out = relu(aggmean @ Wl^T + b + x @ Wr^T) ----
#define WPAD 68
__global__ __launch_bounds__(256)
void node_k(const float* __restrict__ xin, const float* __restrict__ agg,
            const float* __restrict__ Wl, const float* __restrict__ bl,
            const float* __restrict__ Wr, float* __restrict__ hout,
            const int* __restrict__ batch, int n_nodes) {
    __shared__ __align__(16) float wlT[DIM * WPAD];
    __shared__ __align__(16) float wrT[DIM * WPAD];
    __shared__ float bsh[DIM];
    __shared__ __align__(16) float ash[16 * DIM];
    __shared__ __align__(16) float xsh[16 * DIM];

    int tid = threadIdx.x;
    for (int i = tid; i < DIM * DIM; i += 256) {
        int o = i >> 6, k = i & 63;
        wlT[k * WPAD + o] = Wl[i];
        wrT[k * WPAD + o] = Wr[i];
    }
    if (tid < DIM) bsh[tid] = bl[tid];

    int base = blockIdx.x * 128;
    int q = tid & 15;
    int n = tid >> 4;

    for (int r = 0; r < 8; r++) {
        int nb = base + r * 16;
        __syncthreads();
        {
            long long gi = (long long)nb * DIM + tid * 4;
            float4 va = make_float4(0.f, 0.f, 0.f, 0.f), vx = va;
            if (gi + 3 < (long long)n_nodes * DIM) {
                va = *(const float4*)(agg + gi);
                vx = *(const float4*)(xin + gi);
            }
            *(float4*)&ash[tid * 4] = va;
            *(float4*)&xsh[tid * 4] = vx;
        }
        __syncthreads();

        int node = nb + n;
        if (node < n_nodes) {
            const float* ap = &ash[n * DIM];
            const float* xp = &xsh[n * DIM];
            unsigned long long al0 = 0, al1 = 0, ar0 = 0, ar1 = 0;
#pragma unroll
            for (int k = 0; k < DIM; k++) {
                unsigned long long av2 = pack2(ap[k]);
                unsigned long long xv2 = pack2(xp[k]);
                double2 wl = *(const double2*)&wlT[k * WPAD + 4 * q];
                double2 wr = *(const double2*)&wrT[k * WPAD + 4 * q];
                FMA2(al0, av2, __double_as_longlong(wl.x));
                FMA2(al1, av2, __double_as_longlong(wl.y));
                FMA2(ar0, xv2, __double_as_longlong(wr.x));
                FMA2(ar1, xv2, __double_as_longlong(wr.y));
            }
            float l0, l1, l2, l3, r0, r1, r2, r3;
            unpack2(al0, l0, l1); unpack2(al1, l2, l3);
            unpack2(ar0, r0, r1); unpack2(ar1, r2, r3);
            float4 res;
            res.x = fmaxf(l0 + r0 + bsh[4 * q + 0], 0.f);
            res.y = fmaxf(l1 + r1 + bsh[4 * q + 1], 0.f);
            res.z = fmaxf(l2 + r2 + bsh[4 * q + 2], 0.f);
            res.w = fmaxf(l3 + r3 + bsh[4 * q + 3], 0.f);
            if (batch) {
                int g = batch[node];
                red_add_v4(&d_pool[(size_t)g * DIM + 4 * q], res);
            } else {
                *(float4*)&hout[(size_t)node * DIM + 4 * q] = res;
            }
        }
    }
}

// ---- pooled mean -> fc -> log_softmax ----
__global__ void final_k(const float* __restrict__ fcW, const float* __restrict__ fcb,
                        float* __restrict__ out, int G) {
    int g = blockIdx.x * blockDim.x + threadIdx.x;
    if (g >= G) return;
    float inv = 1.f / fmaxf(d_gcnt[g], 1.f);
    float p[DIM];
    const float* pr = &d_pool[(size_t)g * DIM];
#pragma unroll
    for (int k = 0; k < DIM; k++) p[k] = pr[k] * inv;
    float lg[ODIM];
#pragma unroll
    for (int o = 0; o < ODIM; o++) {
        float s = fcb[o];
        const float* w = &fcW[o * DIM];
#pragma unroll
        for (int k = 0; k < DIM; k++) s = fmaf(p[k], w[k], s);
        lg[o] = s;
    }
    float m = lg[0];
#pragma unroll
    for (int o = 1; o < ODIM; o++) m = fmaxf(m, lg[o]);
    float se = 0.f;
#pragma unroll
    for (int o = 0; o < ODIM; o++) se += expf(lg[o] - m);
    float lse = m + logf(se);
#pragma unroll
    for (int o = 0; o < ODIM; o++) out[g * ODIM + o] = lg[o] - lse;
}

extern "C" void kernel_launch(void* const* d_in, const int* in_sizes, int n_in,
                              void* d_out, int out_size) {
    const float* x   = (const float*)d_in[0];
    const float* W1l = (const float*)d_in[1];
    const float* b1  = (const float*)d_in[2];
    const float* W1r = (const float*)d_in[3];
    const float* W2l = (const float*)d_in[4];
    const float* b2  = (const float*)d_in[5];
    const float* W2r = (const float*)d_in[6];
    const float* fcW = (const float*)d_in[7];
    const float* fcb = (const float*)d_in[8];
    const int* ei    = (const int*)d_in[9];     // int32 (JAX x64 disabled)
    const int* batch = (const int*)d_in[10];

    int N = in_sizes[10];
    int E = in_sizes[9] / 2;
    int G = out_size / ODIM;
    int NB = (N + 255) / 256;

    float *agg, *h1, *pool, *gcnt;
    int *deg;
    cudaGetSymbolAddress((void**)&agg,  d_agg);
    cudaGetSymbolAddress((void**)&h1,   d_h1);
    cudaGetSymbolAddress((void**)&pool, d_pool);
    cudaGetSymbolAddress((void**)&gcnt, d_gcnt);
    cudaGetSymbolAddress((void**)&deg,  d_deg);

    // init + CSR build (reused by both layers)
    zero_f<<<32, 256>>>(pool, G * DIM);
    zero_f<<<1, 256>>>(gcnt, G);
    zero_i<<<NB, 256>>>(deg, N);
    gcnt_k<<<NB, 256>>>(batch, N);
    count_k<<<(E + 255) / 256, 256>>>(ei, E);
    scan1_k<<<NB, 256>>>(N);
    scan2_k<<<1, NB_SCAN>>>(NB);
    scan3_k<<<NB, 256>>>(N, E);
    fill_k<<<(E + 255) / 256, 256>>>(ei, E);

    // layer 1
    gather_k<<<(N * 16 + 255) / 256, 256>>>(x, agg, N);
    node_k<<<(N + 127) / 128, 256>>>(x, agg, W1l, b1, W1r, h1, nullptr, N);

    // layer 2
    gather_k<<<(N * 16 + 255) / 256, 256>>>(h1, agg, N);
    node_k<<<(N + 127) / 128, 256>>>(h1, agg, W2l, b2, W2r, nullptr, batch, N);

    // pool -> fc -> log_softmax
    final_k<<<(G + 255) / 256, 256>>>(fcW, fcb, (float*)d_out, G);
}

// round 5
// speedup vs baseline: 1.8470x; 1.0309x over previous
#include <cuda_runtime.h>
#include <cstdint>

#define DIM   64
#define ODIM  16
#define NMAX  100000
#define EMAX  1600000
#define GMAX  512
#define NB_SCAN 512

// ---- scratch (no allocations allowed; __device__ globals per rules) ----
__device__ __align__(16) float d_agg[(size_t)NMAX * DIM];
__device__ __align__(16) float d_h1 [(size_t)NMAX * DIM];
__device__ __align__(16) float d_pool[(size_t)GMAX * DIM];
__device__ float d_gcnt[GMAX];
__device__ int d_deg[NMAX];
__device__ int d_off[NMAX + 1];
__device__ int d_cur[NMAX];
__device__ int d_col[EMAX];
__device__ int d_bsum[NB_SCAN];

// ---- helpers ----
__device__ __forceinline__ void red_add_v4(float* p, float4 v) {
    asm volatile("red.global.add.v4.f32 [%0], {%1,%2,%3,%4};"
                 :: "l"(p), "f"(v.x), "f"(v.y), "f"(v.z), "f"(v.w) : "memory");
}
__device__ __forceinline__ unsigned long long pack2(float v) {
    unsigned long long r;
    asm("mov.b64 %0, {%1,%1};" : "=l"(r) : "r"(__float_as_uint(v)));
    return r;
}
__device__ __forceinline__ void unpack2(unsigned long long v, float& lo, float& hi) {
    unsigned int a, b;
    asm("mov.b64 {%0,%1}, %2;" : "=r"(a), "=r"(b) : "l"(v));
    lo = __uint_as_float(a); hi = __uint_as_float(b);
}
#define FMA2(acc, a, b) \
    asm("fma.rn.f32x2 %0, %1, %2, %0;" : "+l"(acc) : "l"(a), "l"(b))

// ---- init: zero deg + pool in one launch ----
__global__ void init_k(int n, int gp) {
    int i = blockIdx.x * blockDim.x + threadIdx.x;
    int st = gridDim.x * blockDim.x;
    for (int j = i; j < n; j += st) d_deg[j] = 0;
    for (int j = i; j < gp; j += st) d_pool[j] = 0.f;
}

// ---- group counts via binary search (batch is sorted; no atomics) ----
__global__ void gcnt_bs_k(const int* __restrict__ batch, int n, int G) {
    int g = blockIdx.x * blockDim.x + threadIdx.x;
    if (g >= G) return;
    int lo = 0, hi = n;
    while (lo < hi) { int m = (lo + hi) >> 1; if (batch[m] < g) lo = m + 1; else hi = m; }
    int lo2 = lo, hi2 = n;
    while (lo2 < hi2) { int m = (lo2 + hi2) >> 1; if (batch[m] < g + 1) lo2 = m + 1; else hi2 = m; }
    d_gcnt[g] = (float)(lo2 - lo);
}

// ---- CSR build ----
__global__ void count_k(const int* __restrict__ ei, int E) {
    int e = blockIdx.x * blockDim.x + threadIdx.x;
    if (e < E) atomicAdd(&d_deg[ei[E + e]], 1);
}
// level-1: per-256-block exclusive scan of deg -> off (partial), totals -> bsum
__global__ void scan1_k(int n) {
    __shared__ int sh[256];
    int tid = threadIdx.x;
    int i = blockIdx.x * 256 + tid;
    int v = (i < n) ? d_deg[i] : 0;
    sh[tid] = v;
    __syncthreads();
#pragma unroll
    for (int o = 1; o < 256; o <<= 1) {
        int t = (tid >= o) ? sh[tid - o] : 0;
        __syncthreads();
        if (tid >= o) sh[tid] += t;
        __syncthreads();
    }
    if (i < n) d_off[i] = sh[tid] - v;
    if (tid == 255) d_bsum[blockIdx.x] = sh[255];
}
// fused level-2+3: each block sums bsum[0..b) itself, then finalizes offsets+cursors
__global__ void scan23_k(int n, int E) {
    __shared__ int red[8];
    __shared__ int sprev;
    int b = blockIdx.x;
    int tid = threadIdx.x;
    int s = 0;
    for (int j = tid; j < b; j += 256) s += d_bsum[j];
#pragma unroll
    for (int o = 16; o; o >>= 1) s += __shfl_xor_sync(0xffffffffu, s, o);
    if ((tid & 31) == 0) red[tid >> 5] = s;
    __syncthreads();
    if (tid == 0) {
        int t = 0;
#pragma unroll
        for (int w = 0; w < 8; w++) t += red[w];
        sprev = t;
    }
    __syncthreads();
    int i = b * 256 + tid;
    if (i < n) {
        int o = d_off[i] + sprev;
        d_off[i] = o;
        d_cur[i] = o;
    }
    if (b == 0 && tid == 0) d_off[n] = E;
}
__global__ void fill_k(const int* __restrict__ ei, int E) {
    int e = blockIdx.x * blockDim.x + threadIdx.x;
    if (e >= E) return;
    int s = ei[e];
    int d = ei[E + e];
    int p = atomicAdd(&d_cur[d], 1);
    d_col[p] = s;
}

// ---- gather aggregation: warp per node, 2 edges per LDG.128 sweep ----
// lanes 0-15 own edge e, lanes 16-31 own edge e+1; each lane loads one float4
// column of its edge's src row. Final shfl_xor(16) combines the two halves.
__global__ __launch_bounds__(256)
void gather_k(const float* __restrict__ feat, float* __restrict__ agg, int N) {
    int node = (blockIdx.x * 256 + threadIdx.x) >> 5;
    int lane = threadIdx.x & 31;
    if (node >= N) return;
    int beg = d_off[node];
    int end = d_off[node + 1];
    int half = lane >> 4;     // which of the edge pair
    int col4 = lane & 15;     // float4 column within the 64-float row
    float4 acc = make_float4(0.f, 0.f, 0.f, 0.f);
    int e = beg;
    for (; e + 8 <= end; e += 8) {            // 8 edges in flight (4 LDG.128/lane)
        int c0 = __ldg(&d_col[e     + half]);
        int c1 = __ldg(&d_col[e + 2 + half]);
        int c2 = __ldg(&d_col[e + 4 + half]);
        int c3 = __ldg(&d_col[e + 6 + half]);
        float4 v0 = __ldg((const float4*)(feat + (size_t)c0 * DIM) + col4);
        float4 v1 = __ldg((const float4*)(feat + (size_t)c1 * DIM) + col4);
        float4 v2 = __ldg((const float4*)(feat + (size_t)c2 * DIM) + col4);
        float4 v3 = __ldg((const float4*)(feat + (size_t)c3 * DIM) + col4);
        acc.x += (v0.x + v1.x) + (v2.x + v3.x);
        acc.y += (v0.y + v1.y) + (v2.y + v3.y);
        acc.z += (v0.z + v1.z) + (v2.z + v3.z);
        acc.w += (v0.w + v1.w) + (v2.w + v3.w);
    }
    for (; e + 2 <= end; e += 2) {
        int c = __ldg(&d_col[e + half]);
        float4 v = __ldg((const float4*)(feat + (size_t)c * DIM) + col4);
        acc.x += v.x; acc.y += v.y; acc.z += v.z; acc.w += v.w;
    }
    if (e < end && half == 0) {               // odd remainder edge
        int c = __ldg(&d_col[e]);
        float4 v = __ldg((const float4*)(feat + (size_t)c * DIM) + col4);
        acc.x += v.x; acc.y += v.y; acc.z += v.z; acc.w += v.w;
    }
    acc.x += __shfl_xor_sync(0xffffffffu, acc.x, 16);
    acc.y += __shfl_xor_sync(0xffffffffu, acc.y, 16);
    acc.z += __shfl_xor_sync(0xffffffffu, acc.z, 16);
    acc.w += __shfl_xor_sync(0xffffffffu, acc.w, 16);
    if (half == 0) {
        float inv = 1.f / (float)max(end - beg, 1);
        acc.x *= inv; acc.y *= inv; acc.z *= inv; acc.w *= inv;
        *(float4*)(agg + (size_t)node * DIM + col4 * 4) = acc;
    }
}

// ---- fused SAGE node update: out = relu(aggmean @ Wl^T + b + x @ Wr^T) ----
#define WPAD 68
__global__ __launch_bounds__(256)
void node_k(const float* __restrict__ xin, const float* __restrict__ agg,
            const float* __restrict__ Wl, const float* __restrict__ bl,
            const float* __restrict__ Wr, float* __restrict__ hout,
            const int* __restrict__ batch, int n_nodes) {
    __shared__ __align__(16) float wlT[DIM * WPAD];
    __shared__ __align__(16) float wrT[DIM * WPAD];
    __shared__ float bsh[DIM];
    __shared__ __align__(16) float ash[16 * DIM];
    __shared__ __align__(16) float xsh[16 * DIM];

    int tid = threadIdx.x;
    for (int i = tid; i < DIM * DIM; i += 256) {
        int o = i >> 6, k = i & 63;
        wlT[k * WPAD + o] = Wl[i];
        wrT[k * WPAD + o] = Wr[i];
    }
    if (tid < DIM) bsh[tid] = bl[tid];

    int base = blockIdx.x * 128;
    int q = tid & 15;
    int n = tid >> 4;

    for (int r = 0; r < 8; r++) {
        int nb = base + r * 16;
        __syncthreads();
        {
            long long gi = (long long)nb * DIM + tid * 4;
            float4 va = make_float4(0.f, 0.f, 0.f, 0.f), vx = va;
            if (gi + 3 < (long long)n_nodes * DIM) {
                va = *(const float4*)(agg + gi);
                vx = *(const float4*)(xin + gi);
            }
            *(float4*)&ash[tid * 4] = va;
            *(float4*)&xsh[tid * 4] = vx;
        }
        __syncthreads();

        int node = nb + n;
        if (node < n_nodes) {
            const float* ap = &ash[n * DIM];
            const float* xp = &xsh[n * DIM];
            unsigned long long al0 = 0, al1 = 0, ar0 = 0, ar1 = 0;
#pragma unroll
            for (int k = 0; k < DIM; k++) {
                unsigned long long av2 = pack2(ap[k]);
                unsigned long long xv2 = pack2(xp[k]);
                double2 wl = *(const double2*)&wlT[k * WPAD + 4 * q];
                double2 wr = *(const double2*)&wrT[k * WPAD + 4 * q];
                FMA2(al0, av2, __double_as_longlong(wl.x));
                FMA2(al1, av2, __double_as_longlong(wl.y));
                FMA2(ar0, xv2, __double_as_longlong(wr.x));
                FMA2(ar1, xv2, __double_as_longlong(wr.y));
            }
            float l0, l1, l2, l3, r0, r1, r2, r3;
            unpack2(al0, l0, l1); unpack2(al1, l2, l3);
            unpack2(ar0, r0, r1); unpack2(ar1, r2, r3);
            float4 res;
            res.x = fmaxf(l0 + r0 + bsh[4 * q + 0], 0.f);
            res.y = fmaxf(l1 + r1 + bsh[4 * q + 1], 0.f);
            res.z = fmaxf(l2 + r2 + bsh[4 * q + 2], 0.f);
            res.w = fmaxf(l3 + r3 + bsh[4 * q + 3], 0.f);
            if (batch) {
                int g = batch[node];
                red_add_v4(&d_pool[(size_t)g * DIM + 4 * q], res);
            } else {
                *(float4*)&hout[(size_t)node * DIM + 4 * q] = res;
            }
        }
    }
}

// ---- pooled mean -> fc -> log_softmax ----
__global__ void final_k(const float* __restrict__ fcW, const float* __restrict__ fcb,
                        float* __restrict__ out, int G) {
    int g = blockIdx.x * blockDim.x + threadIdx.x;
    if (g >= G) return;
    float inv = 1.f / fmaxf(d_gcnt[g], 1.f);
    float p[DIM];
    const float* pr = &d_pool[(size_t)g * DIM];
#pragma unroll
    for (int k = 0; k < DIM; k++) p[k] = pr[k] * inv;
    float lg[ODIM];
#pragma unroll
    for (int o = 0; o < ODIM; o++) {
        float s = fcb[o];
        const float* w = &fcW[o * DIM];
#pragma unroll
        for (int k = 0; k < DIM; k++) s = fmaf(p[k], w[k], s);
        lg[o] = s;
    }
    float m = lg[0];
#pragma unroll
    for (int o = 1; o < ODIM; o++) m = fmaxf(m, lg[o]);
    float se = 0.f;
#pragma unroll
    for (int o = 0; o < ODIM; o++) se += expf(lg[o] - m);
    float lse = m + logf(se);
#pragma unroll
    for (int o = 0; o < ODIM; o++) out[g * ODIM + o] = lg[o] - lse;
}

extern "C" void kernel_launch(void* const* d_in, const int* in_sizes, int n_in,
                              void* d_out, int out_size) {
    const float* x   = (const float*)d_in[0];
    const float* W1l = (const float*)d_in[1];
    const float* b1  = (const float*)d_in[2];
    const float* W1r = (const float*)d_in[3];
    const float* W2l = (const float*)d_in[4];
    const float* b2  = (const float*)d_in[5];
    const float* W2r = (const float*)d_in[6];
    const float* fcW = (const float*)d_in[7];
    const float* fcb = (const float*)d_in[8];
    const int* ei    = (const int*)d_in[9];     // int32 (JAX x64 disabled)
    const int* batch = (const int*)d_in[10];

    int N = in_sizes[10];
    int E = in_sizes[9] / 2;
    int G = out_size / ODIM;
    int NB = (N + 255) / 256;

    float *agg, *h1;
    cudaGetSymbolAddress((void**)&agg, d_agg);
    cudaGetSymbolAddress((void**)&h1,  d_h1);

    // CSR build (reused by both layers). Launch order keeps gather_k as the
    // 6th launch so ncu (-s 5 -c 1) profiles it.
    init_k<<<NB, 256>>>(N, G * DIM);                      // 1
    count_k<<<(E + 255) / 256, 256>>>(ei, E);             // 2
    scan1_k<<<NB, 256>>>(N);                              // 3
    scan23_k<<<NB, 256>>>(N, E);                          // 4
    fill_k<<<(E + 255) / 256, 256>>>(ei, E);              // 5

    // layer 1
    gather_k<<<(N + 7) / 8, 256>>>(x, agg, N);            // 6 <- profiled
    node_k<<<(N + 127) / 128, 256>>>(x, agg, W1l, b1, W1r, h1, nullptr, N);

    // layer 2
    gather_k<<<(N + 7) / 8, 256>>>(h1, agg, N);
    node_k<<<(N + 127) / 128, 256>>>(h1, agg, W2l, b2, W2r, nullptr, batch, N);

    // pool -> fc -> log_softmax
    gcnt_bs_k<<<(G + 255) / 256, 256>>>(batch, N, G);
    final_k<<<(G + 255) / 256, 256>>>(fcW, fcb, (float*)d_out, G);
}

// round 6
// speedup vs baseline: 2.3208x; 1.2565x over previous
#include <cuda_runtime.h>
#include <cstdint>

#define DIM   64
#define ODIM  16
#define NMAX  100000
#define EMAX  1600000
#define GMAX  512
#define NB_SCAN 512

// ---- scratch (no allocations allowed; __device__ globals per rules) ----
__device__ __align__(16) float d_agg[(size_t)NMAX * DIM];
__device__ __align__(16) float d_h1 [(size_t)NMAX * DIM];
__device__ __align__(16) float d_pool[(size_t)GMAX * DIM];
__device__ float d_gcnt[GMAX];
__device__ int d_deg[NMAX];
__device__ int d_off[NMAX + 1];
__device__ int d_cur[NMAX];
__device__ int d_col[EMAX];
__device__ int d_bsum[NB_SCAN];

// ---- helpers ----
__device__ __forceinline__ void red_add_v4(float* p, float4 v) {
    asm volatile("red.global.add.v4.f32 [%0], {%1,%2,%3,%4};"
                 :: "l"(p), "f"(v.x), "f"(v.y), "f"(v.z), "f"(v.w) : "memory");
}
__device__ __forceinline__ unsigned long long pack2(float v) {
    unsigned long long r;
    asm("mov.b64 %0, {%1,%1};" : "=l"(r) : "r"(__float_as_uint(v)));
    return r;
}
__device__ __forceinline__ void unpack2(unsigned long long v, float& lo, float& hi) {
    unsigned int a, b;
    asm("mov.b64 {%0,%1}, %2;" : "=r"(a), "=r"(b) : "l"(v));
    lo = __uint_as_float(a); hi = __uint_as_float(b);
}
#define FMA2(acc, a, b) \
    asm("fma.rn.f32x2 %0, %1, %2, %0;" : "+l"(acc) : "l"(a), "l"(b))

// ---- init: zero deg + pool, group counts via binary search (batch sorted) ----
__global__ void init_k(const int* __restrict__ batch, int n, int G) {
    int i = blockIdx.x * blockDim.x + threadIdx.x;
    int st = gridDim.x * blockDim.x;
    for (int j = i; j < n; j += st) d_deg[j] = 0;
    for (int j = i; j < G * DIM; j += st) d_pool[j] = 0.f;
    if (i < G) {
        int lo = 0, hi = n;
        while (lo < hi) { int m = (lo + hi) >> 1; if (batch[m] < i) lo = m + 1; else hi = m; }
        int lo2 = lo, hi2 = n;
        while (lo2 < hi2) { int m = (lo2 + hi2) >> 1; if (batch[m] < i + 1) lo2 = m + 1; else hi2 = m; }
        d_gcnt[i] = (float)(lo2 - lo);
    }
}

// ---- CSR build ----
__global__ void count_k(const int* __restrict__ ei, int E) {
    int e = blockIdx.x * blockDim.x + threadIdx.x;
    if (e < E) atomicAdd(&d_deg[ei[E + e]], 1);
}
__global__ void scan1_k(int n) {
    __shared__ int sh[256];
    int tid = threadIdx.x;
    int i = blockIdx.x * 256 + tid;
    int v = (i < n) ? d_deg[i] : 0;
    sh[tid] = v;
    __syncthreads();
#pragma unroll
    for (int o = 1; o < 256; o <<= 1) {
        int t = (tid >= o) ? sh[tid - o] : 0;
        __syncthreads();
        if (tid >= o) sh[tid] += t;
        __syncthreads();
    }
    if (i < n) d_off[i] = sh[tid] - v;
    if (tid == 255) d_bsum[blockIdx.x] = sh[255];
}
__global__ void scan23_k(int n, int E) {
    __shared__ int red[8];
    __shared__ int sprev;
    int b = blockIdx.x;
    int tid = threadIdx.x;
    int s = 0;
    for (int j = tid; j < b; j += 256) s += d_bsum[j];
#pragma unroll
    for (int o = 16; o; o >>= 1) s += __shfl_xor_sync(0xffffffffu, s, o);
    if ((tid & 31) == 0) red[tid >> 5] = s;
    __syncthreads();
    if (tid == 0) {
        int t = 0;
#pragma unroll
        for (int w = 0; w < 8; w++) t += red[w];
        sprev = t;
    }
    __syncthreads();
    int i = b * 256 + tid;
    if (i < n) {
        int o = d_off[i] + sprev;
        d_off[i] = o;
        d_cur[i] = o;
    }
    if (b == 0 && tid == 0) d_off[n] = E;
}
__global__ void fill_k(const int* __restrict__ ei, int E) {
    int e = blockIdx.x * blockDim.x + threadIdx.x;
    if (e >= E) return;
    int s = ei[e];
    int d = ei[E + e];
    int p = atomicAdd(&d_cur[d], 1);
    d_col[p] = s;
}

// ---- gather: warp per node. Indices batch-loaded (coalesced, one LDG for 32),
//      broadcast via shfl, so data LDG.128s issue back-to-back (no idx->data chain). ----
__global__ __launch_bounds__(256)
void gather_k(const float* __restrict__ feat, float* __restrict__ agg, int N) {
    int node = (blockIdx.x * 256 + threadIdx.x) >> 5;
    int lane = threadIdx.x & 31;
    if (node >= N) return;
    int beg = d_off[node];
    int end = d_off[node + 1];
    int half = lane >> 4;
    int col4 = lane & 15;
    const float4* f4 = (const float4*)feat;
    float4 acc = make_float4(0.f, 0.f, 0.f, 0.f);
    for (int b = beg; b < end; b += 32) {
        int m = min(32, end - b);
        int idx = (lane < m) ? __ldg(&d_col[b + lane]) : 0;
        int j = 0;
        for (; j + 8 <= m; j += 8) {
            int c0 = __shfl_sync(0xffffffffu, idx, j     + half);
            int c1 = __shfl_sync(0xffffffffu, idx, j + 2 + half);
            int c2 = __shfl_sync(0xffffffffu, idx, j + 4 + half);
            int c3 = __shfl_sync(0xffffffffu, idx, j + 6 + half);
            float4 v0 = __ldg(f4 + (size_t)c0 * 16 + col4);
            float4 v1 = __ldg(f4 + (size_t)c1 * 16 + col4);
            float4 v2 = __ldg(f4 + (size_t)c2 * 16 + col4);
            float4 v3 = __ldg(f4 + (size_t)c3 * 16 + col4);
            acc.x += (v0.x + v1.x) + (v2.x + v3.x);
            acc.y += (v0.y + v1.y) + (v2.y + v3.y);
            acc.z += (v0.z + v1.z) + (v2.z + v3.z);
            acc.w += (v0.w + v1.w) + (v2.w + v3.w);
        }
        for (; j + 2 <= m; j += 2) {
            int c = __shfl_sync(0xffffffffu, idx, j + half);
            float4 v = __ldg(f4 + (size_t)c * 16 + col4);
            acc.x += v.x; acc.y += v.y; acc.z += v.z; acc.w += v.w;
        }
        if (j < m) {   // odd remainder edge (uniform branch; shfl full-warp)
            int c = __shfl_sync(0xffffffffu, idx, m - 1);
            if (half == 0) {
                float4 v = __ldg(f4 + (size_t)c * 16 + col4);
                acc.x += v.x; acc.y += v.y; acc.z += v.z; acc.w += v.w;
            }
        }
    }
    acc.x += __shfl_xor_sync(0xffffffffu, acc.x, 16);
    acc.y += __shfl_xor_sync(0xffffffffu, acc.y, 16);
    acc.z += __shfl_xor_sync(0xffffffffu, acc.z, 16);
    acc.w += __shfl_xor_sync(0xffffffffu, acc.w, 16);
    if (half == 0) {
        float inv = 1.f / (float)max(end - beg, 1);
        acc.x *= inv; acc.y *= inv; acc.z *= inv; acc.w *= inv;
        *(float4*)(agg + (size_t)node * DIM + col4 * 4) = acc;
    }
}

// ---- fused SAGE node update, 2-node register tiling ----
// Weights stored rotated: row k holds W^T[k][o] at float offset ((o + 4k) & 63).
// Writes: 4-way bank conflict (one-time). Compute reads: 16 distinct float4 per
// instruction, stride 16B -> conflict-free, 16B-aligned. Each weight double2
// read feeds 2 nodes -> half the smem weight bytes per MAC.
__global__ __launch_bounds__(256)
void node_k(const float* __restrict__ xin, const float* __restrict__ agg,
            const float* __restrict__ Wl, const float* __restrict__ bl,
            const float* __restrict__ Wr, float* __restrict__ hout,
            const int* __restrict__ batch, int n_nodes) {
    __shared__ __align__(16) float wlT[DIM * DIM];     // 16 KB
    __shared__ __align__(16) float wrT[DIM * DIM];     // 16 KB
    __shared__ __align__(16) float ash[32 * DIM];      // 8 KB
    __shared__ __align__(16) float xsh[32 * DIM];      // 8 KB  (total 48 KB)

    int tid = threadIdx.x;
    for (int i = tid; i < DIM * DIM; i += 256) {
        int o = i >> 6, k = i & 63;
        int rot = (o + 4 * k) & 63;
        wlT[k * DIM + rot] = Wl[i];
        wrT[k * DIM + rot] = Wr[i];
    }
    int q = tid & 15;
    int s = tid >> 4;
    float4 bq = *(const float4*)(bl + 4 * q);   // bias in registers

    const float4* agg4 = (const float4*)agg;
    const float4* x4   = (const float4*)xin;
    int base = blockIdx.x * 128;

    for (int r = 0; r < 4; r++) {
        int nb = base + r * 32;
        __syncthreads();
        {   // stage 32 rows of agg and x (contiguous 8KB each)
            long long g0 = (long long)nb * 16 + tid;
            long long g1 = g0 + 256;
            long long lim = (long long)n_nodes * 16;
            float4 z = make_float4(0.f, 0.f, 0.f, 0.f);
            ((float4*)ash)[tid]       = (g0 < lim) ? agg4[g0] : z;
            ((float4*)xsh)[tid]       = (g0 < lim) ? x4[g0]   : z;
            ((float4*)ash)[tid + 256] = (g1 < lim) ? agg4[g1] : z;
            ((float4*)xsh)[tid + 256] = (g1 < lim) ? x4[g1]   : z;
        }
        __syncthreads();

        int n0 = nb + s, n1 = nb + s + 16;
        const float* ap0 = &ash[s * DIM];
        const float* xp0 = &xsh[s * DIM];
        const float* ap1 = &ash[(s + 16) * DIM];
        const float* xp1 = &xsh[(s + 16) * DIM];
        unsigned long long a0l0 = 0, a0l1 = 0, a0r0 = 0, a0r1 = 0;
        unsigned long long a1l0 = 0, a1l1 = 0, a1r0 = 0, a1r1 = 0;
#pragma unroll
        for (int k = 0; k < DIM; k++) {
            int rot = (4 * q + 4 * k) & 63;
            unsigned long long av0 = pack2(ap0[k]);
            unsigned long long xv0 = pack2(xp0[k]);
            unsigned long long av1 = pack2(ap1[k]);
            unsigned long long xv1 = pack2(xp1[k]);
            double2 wl = *(const double2*)&wlT[k * DIM + rot];
            double2 wr = *(const double2*)&wrT[k * DIM + rot];
            FMA2(a0l0, av0, __double_as_longlong(wl.x));
            FMA2(a0l1, av0, __double_as_longlong(wl.y));
            FMA2(a0r0, xv0, __double_as_longlong(wr.x));
            FMA2(a0r1, xv0, __double_as_longlong(wr.y));
            FMA2(a1l0, av1, __double_as_longlong(wl.x));
            FMA2(a1l1, av1, __double_as_longlong(wl.y));
            FMA2(a1r0, xv1, __double_as_longlong(wr.x));
            FMA2(a1r1, xv1, __double_as_longlong(wr.y));
        }
#pragma unroll
        for (int nn = 0; nn < 2; nn++) {
            int node = nn ? n1 : n0;
            if (node >= n_nodes) continue;
            float l0, l1, l2, l3, r0, r1, r2, r3;
            if (nn == 0) {
                unpack2(a0l0, l0, l1); unpack2(a0l1, l2, l3);
                unpack2(a0r0, r0, r1); unpack2(a0r1, r2, r3);
            } else {
                unpack2(a1l0, l0, l1); unpack2(a1l1, l2, l3);
                unpack2(a1r0, r0, r1); unpack2(a1r1, r2, r3);
            }
            float4 res;
            res.x = fmaxf(l0 + r0 + bq.x, 0.f);
            res.y = fmaxf(l1 + r1 + bq.y, 0.f);
            res.z = fmaxf(l2 + r2 + bq.z, 0.f);
            res.w = fmaxf(l3 + r3 + bq.w, 0.f);
            if (batch) {
                int g = batch[node];
                red_add_v4(&d_pool[(size_t)g * DIM + 4 * q], res);
            } else {
                *(float4*)&hout[(size_t)node * DIM + 4 * q] = res;
            }
        }
    }
}

// ---- pooled mean -> fc -> log_softmax ----
__global__ void final_k(const float* __restrict__ fcW, const float* __restrict__ fcb,
                        float* __restrict__ out, int G) {
    int g = blockIdx.x * blockDim.x + threadIdx.x;
    if (g >= G) return;
    float inv = 1.f / fmaxf(d_gcnt[g], 1.f);
    float p[DIM];
    const float* pr = &d_pool[(size_t)g * DIM];
#pragma unroll
    for (int k = 0; k < DIM; k++) p[k] = pr[k] * inv;
    float lg[ODIM];
#pragma unroll
    for (int o = 0; o < ODIM; o++) {
        float s = fcb[o];
        const float* w = &fcW[o * DIM];
#pragma unroll
        for (int k = 0; k < DIM; k++) s = fmaf(p[k], w[k], s);
        lg[o] = s;
    }
    float m = lg[0];
#pragma unroll
    for (int o = 1; o < ODIM; o++) m = fmaxf(m, lg[o]);
    float se = 0.f;
#pragma unroll
    for (int o = 0; o < ODIM; o++) se += expf(lg[o] - m);
    float lse = m + logf(se);
#pragma unroll
    for (int o = 0; o < ODIM; o++) out[g * ODIM + o] = lg[o] - lse;
}

extern "C" void kernel_launch(void* const* d_in, const int* in_sizes, int n_in,
                              void* d_out, int out_size) {
    const float* x   = (const float*)d_in[0];
    const float* W1l = (const float*)d_in[1];
    const float* b1  = (const float*)d_in[2];
    const float* W1r = (const float*)d_in[3];
    const float* W2l = (const float*)d_in[4];
    const float* b2  = (const float*)d_in[5];
    const float* W2r = (const float*)d_in[6];
    const float* fcW = (const float*)d_in[7];
    const float* fcb = (const float*)d_in[8];
    const int* ei    = (const int*)d_in[9];     // int32 (JAX x64 disabled)
    const int* batch = (const int*)d_in[10];

    int N = in_sizes[10];
    int E = in_sizes[9] / 2;
    int G = out_size / ODIM;
    int NB = (N + 255) / 256;

    float *agg, *h1;
    cudaGetSymbolAddress((void**)&agg, d_agg);
    cudaGetSymbolAddress((void**)&h1,  d_h1);

    // CSR build (reused by both layers)
    init_k<<<NB, 256>>>(batch, N, G);
    count_k<<<(E + 255) / 256, 256>>>(ei, E);
    scan1_k<<<NB, 256>>>(N);
    scan23_k<<<NB, 256>>>(N, E);
    fill_k<<<(E + 255) / 256, 256>>>(ei, E);

    // layer 1
    gather_k<<<(N + 7) / 8, 256>>>(x, agg, N);
    node_k<<<(N + 127) / 128, 256>>>(x, agg, W1l, b1, W1r, h1, nullptr, N);

    // layer 2
    gather_k<<<(N + 7) / 8, 256>>>(h1, agg, N);
    node_k<<<(N + 127) / 128, 256>>>(h1, agg, W2l, b2, W2r, nullptr, batch, N);

    // pool -> fc -> log_softmax
    final_k<<<(G + 255) / 256, 256>>>(fcW, fcb, (float*)d_out, G);
}